// round 14
// baseline (speedup 1.0000x reference)
#include <cuda_runtime.h>
#include <cuda_fp16.h>
#include <cstdint>

#define HW     9216
#define IMG_W  96
#define IMG_H  96
#define CCH    192
#define NB     4

// Scratch (no cudaMalloc allowed)
__device__ __half g_x16[(size_t)NB * HW * CCH];          // [b][pix][192] fp16
__device__ __half g_w16[(576 + 192) * CCH];              // w_qkv then w_out, fp16
__device__ __half g_q  [(size_t)NB * HW * CCH];          // [b][24 pg][HW][8] fp16 (pre-scaled by scale/ln2)
__device__ __half g_k  [(size_t)NB * HW * CCH];          // [b][24 pg][HW][8] fp16
__device__ __half g_v  [(size_t)NB * HW * CCH];          // [b][24 pg][HW][8] fp16
__device__ __half g_at [(size_t)NB * HW * CCH];          // [b][pix][192] fp16

// q pre-scale: (1/sqrt(32)) / ln(2)  -> natt uses exp2f directly
#define QSCALE 0.2550868054849892f
#define INV_LN2 1.4426950408889634f

// ============================================================================
// Weight prep: fp32 -> fp16
// ============================================================================
__global__ void prep_weights(const float* __restrict__ w_qkv,
                             const float* __restrict__ w_out) {
    const int i = blockIdx.x * 256 + threadIdx.x;
    const int total = (576 + 192) * CCH;
    if (i >= total) return;
    const float v = (i < 576 * CCH) ? w_qkv[i] : w_out[i - 576 * CCH];
    g_w16[i] = __float2half_rn(v);
}

// ============================================================================
// Transpose: x[b][192][HW] fp32 -> g_x16[b][pix][192] fp16
// ============================================================================
__global__ void transpose_k(const float* __restrict__ x) {
    __shared__ float tile[32][33];
    const int b  = blockIdx.z;
    const int p0 = blockIdx.x * 32, c0 = blockIdx.y * 32;
    const float* xb = x + (size_t)b * CCH * HW;
    __half* tb = g_x16 + (size_t)b * HW * CCH;
    const int tx = threadIdx.x, ty = threadIdx.y;
    #pragma unroll
    for (int j = 0; j < 32; j += 8)
        tile[ty + j][tx] = xb[(size_t)(c0 + ty + j) * HW + p0 + tx];
    __syncthreads();
    #pragma unroll
    for (int j = 0; j < 32; j += 8)
        tb[(size_t)(p0 + ty + j) * CCH + c0 + tx] = __float2half_rn(tile[tx][ty + j]);
}

// ============================================================================
// Wide-N pipelined fp16 GEMM (R13 banked): C[m][n] = sum_k A[m][k]*B[n][k]
//   Tile M=128, N=192, K staged 3x64 with cp.async double buffer.
//   512 threads = 16 warps (4x4), warp tile 32x48, acc 48 fp32 regs.
//   MODE=1: C fp32 [n][HW] channel-major (d_out); grid.x = 1.
//   MODE=2: qkv epilogue; grid.x = 3, blockIdx.x = type (0=q,1=k,2=v).
// ============================================================================
#define RS      144                     // smem tile row stride bytes
#define SM_BO   (128 * RS)              // B offset within buffer: 18432
#define BUFSZ   (SM_BO + 192 * RS)      // 46080 per stage buffer
#define SM_GTOT (2 * BUFSZ)             // 92160 (epilogue staging reuses it)

__device__ __forceinline__ void cp16(uint32_t dst, const void* src) {
    asm volatile("cp.async.cg.shared.global [%0], [%1], 16;"
                 :: "r"(dst), "l"(src));
}
#define CP_COMMIT() asm volatile("cp.async.commit_group;" ::: "memory")
#define CP_WAIT(n)  asm volatile("cp.async.wait_group %0;" :: "n"(n) : "memory")

__device__ __forceinline__ void mma16816(float* c, const uint32_t* a, const uint32_t* b) {
    asm volatile(
        "mma.sync.aligned.m16n8k16.row.col.f32.f16.f16.f32 "
        "{%0,%1,%2,%3}, {%4,%5,%6,%7}, {%8,%9}, {%0,%1,%2,%3};"
        : "+f"(c[0]), "+f"(c[1]), "+f"(c[2]), "+f"(c[3])
        : "r"(a[0]), "r"(a[1]), "r"(a[2]), "r"(a[3]), "r"(b[0]), "r"(b[1]));
}

template<int MODE>
__global__ __launch_bounds__(512, 1)
void mma_gemm(const __half* __restrict__ A, const __half* __restrict__ B,
              float* __restrict__ Cout)
{
    extern __shared__ char smem[];
    const uint32_t sb = (uint32_t)__cvta_generic_to_shared(smem);
    const int t    = threadIdx.x;
    const int wid  = t >> 5, lane = t & 31;
    const int gid  = lane >> 2, tig = lane & 3;
    const int wm   = wid & 3, wn = wid >> 2;
    const int m0   = blockIdx.y * 128;
    const int n0   = blockIdx.x * 192;
    const int b    = blockIdx.z;

    const __half* Ab = A + (size_t)b * HW * CCH + (size_t)m0 * CCH;

    float acc[2][6][4];
    #pragma unroll
    for (int mi = 0; mi < 2; mi++)
        #pragma unroll
        for (int ni = 0; ni < 6; ni++)
            #pragma unroll
            for (int j = 0; j < 4; j++) acc[mi][ni][j] = 0.f;

    auto issue_stage = [&](int s) {
        const int k0 = s * 64;
        const uint32_t base = sb + (s & 1) * BUFSZ;
        #pragma unroll
        for (int i = 0; i < 2; i++) {          // A: 128x64 fp16 = 1024 chunks
            const int idx = t + i * 512;
            const int row = idx >> 3, c8 = (idx & 7) * 8;
            cp16(base + row * RS + c8 * 2, Ab + (size_t)row * CCH + k0 + c8);
        }
        #pragma unroll
        for (int i = 0; i < 3; i++) {          // B: 192x64 fp16 = 1536 chunks
            const int idx = t + i * 512;
            const int row = idx >> 3, c8 = (idx & 7) * 8;
            cp16(base + SM_BO + row * RS + c8 * 2,
                 B + (size_t)(n0 + row) * CCH + k0 + c8);
        }
        CP_COMMIT();
    };

    issue_stage(0);

    #pragma unroll 1
    for (int s = 0; s < 3; s++) {
        if (s < 2) issue_stage(s + 1);
        if (s < 2) { CP_WAIT(1); } else { CP_WAIT(0); }
        __syncthreads();

        const char* cur = smem + (s & 1) * BUFSZ;
        #pragma unroll
        for (int kk = 0; kk < 4; kk++) {
            const uint32_t cb = kk * 32 + tig * 4;
            uint32_t ah[2][4], bh[6][2];
            #pragma unroll
            for (int mi = 0; mi < 2; mi++) {
                const uint32_t r0 = (wm * 32 + mi * 16 + gid) * RS + cb;
                ah[mi][0] = *(const uint32_t*)(cur + r0);
                ah[mi][1] = *(const uint32_t*)(cur + r0 + 8 * RS);
                ah[mi][2] = *(const uint32_t*)(cur + r0 + 16);
                ah[mi][3] = *(const uint32_t*)(cur + r0 + 8 * RS + 16);
            }
            #pragma unroll
            for (int ni = 0; ni < 6; ni++) {
                const uint32_t rn = (wn * 48 + ni * 8 + gid) * RS + cb;
                bh[ni][0] = *(const uint32_t*)(cur + SM_BO + rn);
                bh[ni][1] = *(const uint32_t*)(cur + SM_BO + rn + 16);
            }
            #pragma unroll
            for (int mi = 0; mi < 2; mi++)
                #pragma unroll
                for (int ni = 0; ni < 6; ni++)
                    mma16816(acc[mi][ni], ah[mi], bh[ni]);
        }
        __syncthreads();
    }

    if (MODE == 1) {
        float* Cb = Cout + (size_t)b * CCH * HW;
        #pragma unroll
        for (int mi = 0; mi < 2; mi++) {
            const int row = m0 + wm * 32 + mi * 16 + gid;
            #pragma unroll
            for (int ni = 0; ni < 6; ni++) {
                const int col = n0 + wn * 48 + ni * 8 + 2 * tig;
                Cb[(size_t)col       * HW + row]     = acc[mi][ni][0];
                Cb[(size_t)(col + 1) * HW + row]     = acc[mi][ni][1];
                Cb[(size_t)col       * HW + row + 8] = acc[mi][ni][2];
                Cb[(size_t)(col + 1) * HW + row + 8] = acc[mi][ni][3];
            }
        }
    } else {
        const int type = blockIdx.x;            // 0=q, 1=k, 2=v
        const float sc = (type == 0) ? QSCALE : 1.0f;
        __half* st = (__half*)smem;             // stride 200 halves (400 B)
        #pragma unroll
        for (int mi = 0; mi < 2; mi++) {
            const int rl = wm * 32 + mi * 16 + gid;
            #pragma unroll
            for (int ni = 0; ni < 6; ni++) {
                const int cl = wn * 48 + ni * 8 + 2 * tig;
                *(__half2*)&st[rl * 200 + cl] =
                    __floats2half2_rn(acc[mi][ni][0] * sc, acc[mi][ni][1] * sc);
                *(__half2*)&st[(rl + 8) * 200 + cl] =
                    __floats2half2_rn(acc[mi][ni][2] * sc, acc[mi][ni][3] * sc);
            }
        }
        __syncthreads();
        __half* dst = (type == 0) ? g_q : (type == 1) ? g_k : g_v;
        #pragma unroll
        for (int i = 0; i < 6; i++) {           // 24 pgs x 128 rows = 3072 uint4
            const int idx = i * 512 + t;
            const int r = idx & 127, pg = idx >> 7;
            uint4 val = *(uint4*)&st[r * 200 + pg * 8];
            *(uint4*)&dst[(((size_t)b * 24 + pg) * HW + m0 + r) * 8] = val;
        }
    }
}

// ============================================================================
// Neighborhood attention: branch-free column handling, uniform row skip.
//   OOB rows: l += srow[di] (precomputed sum of exp2(bias) for that row).
//   Valid rows: clamped unconditional k/v loads (batchable LDG stream),
//   SEL-predicated contribution. Grouped fp16 v-accum per row (R12).
// ============================================================================
template<int K, int DIL>
__device__ __forceinline__ void natt_body(const float* __restrict__ sbias,
                                          const float* __restrict__ srow,
                                          int head, int b)
{
    const int w   = blockIdx.x * 32 + threadIdx.x;
    const int h   = blockIdx.y * 4  + threadIdx.y;
    const int pix = h * IMG_W + w;

    const __half* qp = g_q + (((size_t)b * 24 + head * 4) * HW + pix) * 8;
    const __half* kb = g_k + ((size_t)b * 24 + head * 4) * HW * 8;
    const __half* vb = g_v + ((size_t)b * 24 + head * 4) * HW * 8;

    __half2 qh[16];
    #pragma unroll
    for (int j = 0; j < 4; j++) {
        uint4 r = *(const uint4*)(qp + (size_t)j * HW * 8);
        qh[4 * j + 0] = *(const __half2*)&r.x;
        qh[4 * j + 1] = *(const __half2*)&r.y;
        qh[4 * j + 2] = *(const __half2*)&r.z;
        qh[4 * j + 3] = *(const __half2*)&r.w;
    }

    float4 acc[8];
    #pragma unroll
    for (int i = 0; i < 8; i++) acc[i] = make_float4(0.f, 0.f, 0.f, 0.f);
    float l = 0.f;

    #pragma unroll 1
    for (int di = 0; di < K; di++) {
        const int hh = h + (di - K / 2) * DIL;      // warp-uniform
        if ((unsigned)hh >= IMG_H) {                // uniform branch
            l += srow[di];
            continue;
        }

        __half2 a16[16];
        #pragma unroll
        for (int i = 0; i < 16; i++) a16[i] = __float2half2_rn(0.f);

        #pragma unroll
        for (int dj = 0; dj < K; dj++) {
            const int ww = w + (dj - K / 2) * DIL;
            const bool ok = ((unsigned)ww < IMG_W);
            const int wc = min(max(ww, 0), IMG_W - 1);
            const int off = hh * IMG_W + wc;

            // unconditional k loads + HFMA2 dot (batchable)
            const __half* kp = kb + (size_t)off * 8;
            __half2 s0 = __float2half2_rn(0.f);
            __half2 s1 = __float2half2_rn(0.f);
            #pragma unroll
            for (int j = 0; j < 4; j++) {
                uint4 raw = *(const uint4*)(kp + (size_t)j * HW * 8);
                s0 = __hfma2(qh[4 * j + 0], *(const __half2*)&raw.x, s0);
                s1 = __hfma2(qh[4 * j + 1], *(const __half2*)&raw.y, s1);
                s0 = __hfma2(qh[4 * j + 2], *(const __half2*)&raw.z, s0);
                s1 = __hfma2(qh[4 * j + 3], *(const __half2*)&raw.w, s1);
            }
            const float2 sf = __half22float2(__hadd2(s0, s1));
            const float s = sf.x + sf.y;

            const float bias = sbias[di * K + dj];
            const float e = exp2f(ok ? s + bias : bias);
            l += e;
            const float ev = ok ? e : 0.f;
            const __half2 eh = __float2half2_rn(ev);

            // unconditional v loads (eh==0 for OOB lanes)
            const __half* vp = vb + (size_t)off * 8;
            #pragma unroll
            for (int j = 0; j < 4; j++) {
                uint4 raw = *(const uint4*)(vp + (size_t)j * HW * 8);
                a16[4*j+0] = __hfma2(eh, *(const __half2*)&raw.x, a16[4*j+0]);
                a16[4*j+1] = __hfma2(eh, *(const __half2*)&raw.y, a16[4*j+1]);
                a16[4*j+2] = __hfma2(eh, *(const __half2*)&raw.z, a16[4*j+2]);
                a16[4*j+3] = __hfma2(eh, *(const __half2*)&raw.w, a16[4*j+3]);
            }
        }

        #pragma unroll
        for (int j = 0; j < 4; j++) {
            float2 f0 = __half22float2(a16[4*j+0]);
            float2 f1 = __half22float2(a16[4*j+1]);
            float2 f2 = __half22float2(a16[4*j+2]);
            float2 f3 = __half22float2(a16[4*j+3]);
            acc[2*j].x   += f0.x; acc[2*j].y   += f0.y;
            acc[2*j].z   += f1.x; acc[2*j].w   += f1.y;
            acc[2*j+1].x += f2.x; acc[2*j+1].y += f2.y;
            acc[2*j+1].z += f3.x; acc[2*j+1].w += f3.y;
        }
    }

    const float il = 1.f / l;
    const size_t ob = ((size_t)b * HW + pix) * CCH + head * 32;
    #pragma unroll
    for (int j = 0; j < 4; j++) {
        __half2 h0 = __floats2half2_rn(acc[2*j].x   * il, acc[2*j].y   * il);
        __half2 h1 = __floats2half2_rn(acc[2*j].z   * il, acc[2*j].w   * il);
        __half2 h2 = __floats2half2_rn(acc[2*j+1].x * il, acc[2*j+1].y * il);
        __half2 h3 = __floats2half2_rn(acc[2*j+1].z * il, acc[2*j+1].w * il);
        uint4 val;
        val.x = *(uint32_t*)&h0; val.y = *(uint32_t*)&h1;
        val.z = *(uint32_t*)&h2; val.w = *(uint32_t*)&h3;
        *(uint4*)&g_at[ob + j * 8] = val;
    }
}

__global__ __launch_bounds__(128, 6)
void natt_all(const float* __restrict__ b0, const float* __restrict__ b1,
              const float* __restrict__ b2, const float* __restrict__ b3,
              const float* __restrict__ b4, const float* __restrict__ b5)
{
    __shared__ float sb[81];
    __shared__ float srow[9];
    // Heavy heads first: tail of the grid is cheap CTAs.
    const int HORD[6] = {4, 5, 3, 2, 1, 0};
    const int z = blockIdx.z;
    const int head = HORD[z >> 2];
    const int b    = z & 3;
    const float* bp;
    int kk;
    switch (head) {
        case 0: bp = b0; kk = 3; break;
        case 1: bp = b1; kk = 5; break;
        case 2: bp = b2; kk = 7; break;
        case 3: bp = b3; kk = 7; break;
        case 4: bp = b4; kk = 9; break;
        default: bp = b5; kk = 9; break;
    }
    const int t = threadIdx.y * 32 + threadIdx.x;
    if (t < kk * kk) sb[t] = bp[t] * INV_LN2;    // bias in log2 domain
    __syncthreads();
    if (t < kk) {                                // per-row exp-sum for OOB rows
        float s = 0.f;
        for (int j = 0; j < kk; j++) s += exp2f(sb[t * kk + j]);
        srow[t] = s;
    }
    __syncthreads();
    switch (head) {
        case 0: natt_body<3, 1>(sb, srow, 0, b); break;
        case 1: natt_body<5, 2>(sb, srow, 1, b); break;
        case 2: natt_body<7, 1>(sb, srow, 2, b); break;
        case 3: natt_body<7, 3>(sb, srow, 3, b); break;
        case 4: natt_body<9, 1>(sb, srow, 4, b); break;
        case 5: natt_body<9, 2>(sb, srow, 5, b); break;
    }
}

// ============================================================================
extern "C" void kernel_launch(void* const* d_in, const int* in_sizes, int n_in,
                              void* d_out, int out_size)
{
    (void)in_sizes; (void)n_in; (void)out_size;
    const float* x     = (const float*)d_in[0];
    const float* w_qkv = (const float*)d_in[1];
    const float* w_out = (const float*)d_in[2];
    const float* b0 = (const float*)d_in[3];
    const float* b1 = (const float*)d_in[4];
    const float* b2 = (const float*)d_in[5];
    const float* b3 = (const float*)d_in[6];
    const float* b4 = (const float*)d_in[7];
    const float* b5 = (const float*)d_in[8];

    __half *x16, *w16, *at16;
    cudaGetSymbolAddress((void**)&x16,  g_x16);
    cudaGetSymbolAddress((void**)&w16,  g_w16);
    cudaGetSymbolAddress((void**)&at16, g_at);

    cudaFuncSetAttribute(mma_gemm<1>, cudaFuncAttributeMaxDynamicSharedMemorySize, SM_GTOT);
    cudaFuncSetAttribute(mma_gemm<2>, cudaFuncAttributeMaxDynamicSharedMemorySize, SM_GTOT);

    prep_weights<<<(768 * CCH + 255) / 256, 256>>>(w_qkv, w_out);
    transpose_k<<<dim3(HW / 32, CCH / 32, NB), dim3(32, 8)>>>(x);

    // qkv = x16 @ w_qkv^T  -> g_q / g_k / g_v (fp16 d8-packed, q pre-scaled)
    mma_gemm<2><<<dim3(3, HW / 128, NB), 512, SM_GTOT>>>(x16, w16, nullptr);

    natt_all<<<dim3(IMG_W / 32, IMG_H / 4, NB * 6), dim3(32, 4)>>>(
        b0, b1, b2, b3, b4, b5);

    // d_out[b][ch][pix] = (attn @ w_out^T)^T
    mma_gemm<1><<<dim3(1, HW / 128, NB), 512, SM_GTOT>>>(
        at16, w16 + 576 * CCH, (float*)d_out);
}

// round 16
// speedup vs baseline: 1.0526x; 1.0526x over previous
#include <cuda_runtime.h>
#include <cuda_fp16.h>
#include <cstdint>

#define HW     9216
#define IMG_W  96
#define IMG_H  96
#define CCH    192
#define NB     4

// Scratch (no cudaMalloc allowed)
__device__ __half g_w16[(576 + 192) * CCH];              // w_qkv then w_out, fp16
__device__ __half g_q  [(size_t)NB * HW * CCH];          // [b][24 pg][HW][8] fp16 (pre-scaled by scale/ln2)
__device__ __half g_k  [(size_t)NB * HW * CCH];          // [b][24 pg][HW][8] fp16
__device__ __half g_v  [(size_t)NB * HW * CCH];          // [b][24 pg][HW][8] fp16
__device__ __half g_at [(size_t)NB * HW * CCH];          // [b][pix][192] fp16

// q pre-scale: (1/sqrt(32)) / ln(2)  -> natt uses exp2f directly
#define QSCALE 0.2550868054849892f
#define INV_LN2 1.4426950408889634f

// ============================================================================
// Weight prep: fp32 -> fp16
// ============================================================================
__global__ void prep_weights(const float* __restrict__ w_qkv,
                             const float* __restrict__ w_out) {
    const int i = blockIdx.x * 256 + threadIdx.x;
    const int total = (576 + 192) * CCH;
    if (i >= total) return;
    const float v = (i < 576 * CCH) ? w_qkv[i] : w_out[i - 576 * CCH];
    g_w16[i] = __float2half_rn(v);
}

// ============================================================================
// Wide-N pipelined fp16 GEMM: C[m][n] = sum_k A[m][k]*B[n][k]
//   Tile M=128, N=192, K staged 3x64, B via cp.async double buffer.
//   512 threads = 16 warps (4x4), warp tile 32x48, acc 48 fp32 regs.
//   MODE=1: A = g_at fp16 [pix][192] (cp.async loader); C fp32 [n][HW]
//           channel-major (d_out); grid.x = 1.
//   MODE=2: A = x fp32 [192][HW] CHANNEL-MAJOR — fused transpose+convert
//           loader (coalesced LDG.32 per channel row, STS.128 into the same
//           smem layout, reg-prefetched across stages). qkv epilogue;
//           grid.x = 3, blockIdx.x = type (0=q,1=k,2=v).
// ============================================================================
#define RS      144                     // smem tile row stride bytes
#define SM_BO   (128 * RS)              // B offset within buffer: 18432
#define BUFSZ   (SM_BO + 192 * RS)      // 46080 per stage buffer
#define SM_GTOT (2 * BUFSZ)             // 92160 (epilogue staging reuses it)

__device__ __forceinline__ void cp16(uint32_t dst, const void* src) {
    asm volatile("cp.async.cg.shared.global [%0], [%1], 16;"
                 :: "r"(dst), "l"(src));
}
#define CP_COMMIT() asm volatile("cp.async.commit_group;" ::: "memory")
#define CP_WAIT(n)  asm volatile("cp.async.wait_group %0;" :: "n"(n) : "memory")

__device__ __forceinline__ void mma16816(float* c, const uint32_t* a, const uint32_t* b) {
    asm volatile(
        "mma.sync.aligned.m16n8k16.row.col.f32.f16.f16.f32 "
        "{%0,%1,%2,%3}, {%4,%5,%6,%7}, {%8,%9}, {%0,%1,%2,%3};"
        : "+f"(c[0]), "+f"(c[1]), "+f"(c[2]), "+f"(c[3])
        : "r"(a[0]), "r"(a[1]), "r"(a[2]), "r"(a[3]), "r"(b[0]), "r"(b[1]));
}

template<int MODE>
__global__ __launch_bounds__(512, 1)
void mma_gemm(const __half* __restrict__ A16, const float* __restrict__ A32,
              const __half* __restrict__ B, float* __restrict__ Cout)
{
    extern __shared__ char smem[];
    const uint32_t sb = (uint32_t)__cvta_generic_to_shared(smem);
    const int t    = threadIdx.x;
    const int wid  = t >> 5, lane = t & 31;
    const int gid  = lane >> 2, tig = lane & 3;
    const int wm   = wid & 3, wn = wid >> 2;
    const int m0   = blockIdx.y * 128;
    const int n0   = blockIdx.x * 192;
    const int b    = blockIdx.z;

    const __half* Ab16 = (MODE == 1) ? A16 + (size_t)b * HW * CCH + (size_t)m0 * CCH : nullptr;
    const float*  Ab32 = (MODE == 2) ? A32 + (size_t)b * CCH * HW : nullptr;

    float acc[2][6][4];
    #pragma unroll
    for (int mi = 0; mi < 2; mi++)
        #pragma unroll
        for (int ni = 0; ni < 6; ni++)
            #pragma unroll
            for (int j = 0; j < 4; j++) acc[mi][ni][j] = 0.f;

    // fused-transpose A loader state (MODE 2): pixel p, channel group cg
    const int p  = t & 127;
    const int cg = t >> 7;              // 0..3 -> 16 channels each
    float af[16];                       // prefetched A values for next stage

    auto loadA32 = [&](int s) {
        const int k0 = s * 64;
        #pragma unroll
        for (int h8 = 0; h8 < 2; h8++) {
            const int c8 = cg * 16 + h8 * 8;
            #pragma unroll
            for (int j = 0; j < 8; j++)
                af[h8 * 8 + j] = Ab32[(size_t)(k0 + c8 + j) * HW + m0 + p];
        }
    };
    auto stsA32 = [&](int s) {
        const uint32_t base = sb + (s & 1) * BUFSZ;
        #pragma unroll
        for (int h8 = 0; h8 < 2; h8++) {
            const int c8 = cg * 16 + h8 * 8;
            uint4 pk;
            __half2* ph = (__half2*)&pk;
            #pragma unroll
            for (int j = 0; j < 4; j++)
                ph[j] = __floats2half2_rn(af[h8 * 8 + 2 * j], af[h8 * 8 + 2 * j + 1]);
            asm volatile("st.shared.v4.b32 [%0], {%1,%2,%3,%4};"
                :: "r"(base + p * RS + c8 * 2),
                   "r"(pk.x), "r"(pk.y), "r"(pk.z), "r"(pk.w));
        }
    };

    auto issue_stage = [&](int s) {     // B tile + (MODE 1) A tile via cp.async
        const int k0 = s * 64;
        const uint32_t base = sb + (s & 1) * BUFSZ;
        if (MODE == 1) {
            #pragma unroll
            for (int i = 0; i < 2; i++) {      // A: 128x64 fp16 = 1024 chunks
                const int idx = t + i * 512;
                const int row = idx >> 3, c8 = (idx & 7) * 8;
                cp16(base + row * RS + c8 * 2, Ab16 + (size_t)row * CCH + k0 + c8);
            }
        }
        #pragma unroll
        for (int i = 0; i < 3; i++) {          // B: 192x64 fp16 = 1536 chunks
            const int idx = t + i * 512;
            const int row = idx >> 3, c8 = (idx & 7) * 8;
            cp16(base + SM_BO + row * RS + c8 * 2,
                 B + (size_t)(n0 + row) * CCH + k0 + c8);
        }
        CP_COMMIT();
    };

    if (MODE == 2) loadA32(0);
    issue_stage(0);

    #pragma unroll 1
    for (int s = 0; s < 3; s++) {
        if (MODE == 2) stsA32(s);
        if (s < 2) issue_stage(s + 1);
        if (s < 2) { CP_WAIT(1); } else { CP_WAIT(0); }
        __syncthreads();
        if (MODE == 2 && s < 2) loadA32(s + 1);  // overlap with mma below

        const char* cur = smem + (s & 1) * BUFSZ;
        #pragma unroll
        for (int kk = 0; kk < 4; kk++) {
            const uint32_t cb = kk * 32 + tig * 4;
            uint32_t ah[2][4], bh[6][2];
            #pragma unroll
            for (int mi = 0; mi < 2; mi++) {
                const uint32_t r0 = (wm * 32 + mi * 16 + gid) * RS + cb;
                ah[mi][0] = *(const uint32_t*)(cur + r0);
                ah[mi][1] = *(const uint32_t*)(cur + r0 + 8 * RS);
                ah[mi][2] = *(const uint32_t*)(cur + r0 + 16);
                ah[mi][3] = *(const uint32_t*)(cur + r0 + 8 * RS + 16);
            }
            #pragma unroll
            for (int ni = 0; ni < 6; ni++) {
                const uint32_t rn = (wn * 48 + ni * 8 + gid) * RS + cb;
                bh[ni][0] = *(const uint32_t*)(cur + SM_BO + rn);
                bh[ni][1] = *(const uint32_t*)(cur + SM_BO + rn + 16);
            }
            #pragma unroll
            for (int mi = 0; mi < 2; mi++)
                #pragma unroll
                for (int ni = 0; ni < 6; ni++)
                    mma16816(acc[mi][ni], ah[mi], bh[ni]);
        }
        __syncthreads();
    }

    if (MODE == 1) {
        float* Cb = Cout + (size_t)b * CCH * HW;
        #pragma unroll
        for (int mi = 0; mi < 2; mi++) {
            const int row = m0 + wm * 32 + mi * 16 + gid;
            #pragma unroll
            for (int ni = 0; ni < 6; ni++) {
                const int col = n0 + wn * 48 + ni * 8 + 2 * tig;
                Cb[(size_t)col       * HW + row]     = acc[mi][ni][0];
                Cb[(size_t)(col + 1) * HW + row]     = acc[mi][ni][1];
                Cb[(size_t)col       * HW + row + 8] = acc[mi][ni][2];
                Cb[(size_t)(col + 1) * HW + row + 8] = acc[mi][ni][3];
            }
        }
    } else {
        const int type = blockIdx.x;            // 0=q, 1=k, 2=v
        const float sc = (type == 0) ? QSCALE : 1.0f;
        __half* st = (__half*)smem;             // stride 200 halves (400 B)
        #pragma unroll
        for (int mi = 0; mi < 2; mi++) {
            const int rl = wm * 32 + mi * 16 + gid;
            #pragma unroll
            for (int ni = 0; ni < 6; ni++) {
                const int cl = wn * 48 + ni * 8 + 2 * tig;
                *(__half2*)&st[rl * 200 + cl] =
                    __floats2half2_rn(acc[mi][ni][0] * sc, acc[mi][ni][1] * sc);
                *(__half2*)&st[(rl + 8) * 200 + cl] =
                    __floats2half2_rn(acc[mi][ni][2] * sc, acc[mi][ni][3] * sc);
            }
        }
        __syncthreads();
        __half* dst = (type == 0) ? g_q : (type == 1) ? g_k : g_v;
        #pragma unroll
        for (int i = 0; i < 6; i++) {           // 24 pgs x 128 rows = 3072 uint4
            const int idx = i * 512 + t;
            const int r = idx & 127, pg = idx >> 7;
            uint4 val = *(uint4*)&st[r * 200 + pg * 8];
            *(uint4*)&dst[(((size_t)b * 24 + pg) * HW + m0 + r) * 8] = val;
        }
    }
}

// ============================================================================
// Neighborhood attention (R12/R13 banked body): guarded loads, exp2,
// grouped fp16 v-accum per window row, promoted to fp32 once per row.
// ============================================================================
template<int K, int DIL>
__device__ __forceinline__ void natt_body(const float* __restrict__ sbias,
                                          int head, int b)
{
    const int w   = blockIdx.x * 32 + threadIdx.x;
    const int h   = blockIdx.y * 4  + threadIdx.y;
    const int pix = h * IMG_W + w;

    const __half* qp = g_q + (((size_t)b * 24 + head * 4) * HW + pix) * 8;
    const __half* kb = g_k + ((size_t)b * 24 + head * 4) * HW * 8;
    const __half* vb = g_v + ((size_t)b * 24 + head * 4) * HW * 8;

    __half2 qh[16];
    #pragma unroll
    for (int j = 0; j < 4; j++) {
        uint4 r = *(const uint4*)(qp + (size_t)j * HW * 8);
        qh[4 * j + 0] = *(const __half2*)&r.x;
        qh[4 * j + 1] = *(const __half2*)&r.y;
        qh[4 * j + 2] = *(const __half2*)&r.z;
        qh[4 * j + 3] = *(const __half2*)&r.w;
    }

    float4 acc[8];
    #pragma unroll
    for (int i = 0; i < 8; i++) acc[i] = make_float4(0.f, 0.f, 0.f, 0.f);
    float l = 0.f;

    #pragma unroll 1
    for (int di = 0; di < K; di++) {
        const int hh = h + (di - K / 2) * DIL;
        const bool rok = ((unsigned)hh < IMG_H);

        __half2 a16[16];
        #pragma unroll
        for (int i = 0; i < 16; i++) a16[i] = __float2half2_rn(0.f);

        #pragma unroll
        for (int dj = 0; dj < K; dj++) {
            const int ww = w + (dj - K / 2) * DIL;
            const bool ok = rok && ((unsigned)ww < IMG_W);
            const int off = hh * IMG_W + ww;
            float s = 0.f;
            if (ok) {
                const __half* kp = kb + (size_t)off * 8;
                __half2 s0 = __float2half2_rn(0.f);
                __half2 s1 = __float2half2_rn(0.f);
                #pragma unroll
                for (int j = 0; j < 4; j++) {
                    uint4 raw = *(const uint4*)(kp + (size_t)j * HW * 8);
                    s0 = __hfma2(qh[4 * j + 0], *(const __half2*)&raw.x, s0);
                    s1 = __hfma2(qh[4 * j + 1], *(const __half2*)&raw.y, s1);
                    s0 = __hfma2(qh[4 * j + 2], *(const __half2*)&raw.z, s0);
                    s1 = __hfma2(qh[4 * j + 3], *(const __half2*)&raw.w, s1);
                }
                const float2 sf = __half22float2(__hadd2(s0, s1));
                s = sf.x + sf.y;
            }
            const float e = exp2f(s + sbias[di * K + dj]);
            l += e;
            if (ok) {
                const __half2 eh = __float2half2_rn(e);
                const __half* vp = vb + (size_t)off * 8;
                #pragma unroll
                for (int j = 0; j < 4; j++) {
                    uint4 raw = *(const uint4*)(vp + (size_t)j * HW * 8);
                    a16[4*j+0] = __hfma2(eh, *(const __half2*)&raw.x, a16[4*j+0]);
                    a16[4*j+1] = __hfma2(eh, *(const __half2*)&raw.y, a16[4*j+1]);
                    a16[4*j+2] = __hfma2(eh, *(const __half2*)&raw.z, a16[4*j+2]);
                    a16[4*j+3] = __hfma2(eh, *(const __half2*)&raw.w, a16[4*j+3]);
                }
            }
        }

        #pragma unroll
        for (int j = 0; j < 4; j++) {
            float2 f0 = __half22float2(a16[4*j+0]);
            float2 f1 = __half22float2(a16[4*j+1]);
            float2 f2 = __half22float2(a16[4*j+2]);
            float2 f3 = __half22float2(a16[4*j+3]);
            acc[2*j].x   += f0.x; acc[2*j].y   += f0.y;
            acc[2*j].z   += f1.x; acc[2*j].w   += f1.y;
            acc[2*j+1].x += f2.x; acc[2*j+1].y += f2.y;
            acc[2*j+1].z += f3.x; acc[2*j+1].w += f3.y;
        }
    }

    const float il = 1.f / l;
    const size_t ob = ((size_t)b * HW + pix) * CCH + head * 32;
    #pragma unroll
    for (int j = 0; j < 4; j++) {
        __half2 h0 = __floats2half2_rn(acc[2*j].x   * il, acc[2*j].y   * il);
        __half2 h1 = __floats2half2_rn(acc[2*j].z   * il, acc[2*j].w   * il);
        __half2 h2 = __floats2half2_rn(acc[2*j+1].x * il, acc[2*j+1].y * il);
        __half2 h3 = __floats2half2_rn(acc[2*j+1].z * il, acc[2*j+1].w * il);
        uint4 val;
        val.x = *(uint32_t*)&h0; val.y = *(uint32_t*)&h1;
        val.z = *(uint32_t*)&h2; val.w = *(uint32_t*)&h3;
        *(uint4*)&g_at[ob + j * 8] = val;
    }
}

__global__ __launch_bounds__(128, 6)
void natt_all(const float* __restrict__ b0, const float* __restrict__ b1,
              const float* __restrict__ b2, const float* __restrict__ b3,
              const float* __restrict__ b4, const float* __restrict__ b5)
{
    __shared__ float sb[81];
    // Heavy heads first: tail of the grid is cheap CTAs.
    const int HORD[6] = {4, 5, 3, 2, 1, 0};
    const int z = blockIdx.z;
    const int head = HORD[z >> 2];
    const int b    = z & 3;
    const float* bp;
    int k2;
    switch (head) {
        case 0: bp = b0; k2 = 9;  break;
        case 1: bp = b1; k2 = 25; break;
        case 2: bp = b2; k2 = 49; break;
        case 3: bp = b3; k2 = 49; break;
        case 4: bp = b4; k2 = 81; break;
        default: bp = b5; k2 = 81; break;
    }
    const int t = threadIdx.y * 32 + threadIdx.x;
    if (t < k2) sb[t] = bp[t] * INV_LN2;     // bias in log2 domain
    __syncthreads();
    switch (head) {
        case 0: natt_body<3, 1>(sb, 0, b); break;
        case 1: natt_body<5, 2>(sb, 1, b); break;
        case 2: natt_body<7, 1>(sb, 2, b); break;
        case 3: natt_body<7, 3>(sb, 3, b); break;
        case 4: natt_body<9, 1>(sb, 4, b); break;
        case 5: natt_body<9, 2>(sb, 5, b); break;
    }
}

// ============================================================================
extern "C" void kernel_launch(void* const* d_in, const int* in_sizes, int n_in,
                              void* d_out, int out_size)
{
    (void)in_sizes; (void)n_in; (void)out_size;
    const float* x     = (const float*)d_in[0];
    const float* w_qkv = (const float*)d_in[1];
    const float* w_out = (const float*)d_in[2];
    const float* b0 = (const float*)d_in[3];
    const float* b1 = (const float*)d_in[4];
    const float* b2 = (const float*)d_in[5];
    const float* b3 = (const float*)d_in[6];
    const float* b4 = (const float*)d_in[7];
    const float* b5 = (const float*)d_in[8];

    __half *w16, *at16;
    cudaGetSymbolAddress((void**)&w16,  g_w16);
    cudaGetSymbolAddress((void**)&at16, g_at);

    cudaFuncSetAttribute(mma_gemm<1>, cudaFuncAttributeMaxDynamicSharedMemorySize, SM_GTOT);
    cudaFuncSetAttribute(mma_gemm<2>, cudaFuncAttributeMaxDynamicSharedMemorySize, SM_GTOT);

    prep_weights<<<(768 * CCH + 255) / 256, 256>>>(w_qkv, w_out);

    // qkv = x @ w_qkv^T with fused transpose+fp16 convert in the A loader
    mma_gemm<2><<<dim3(3, HW / 128, NB), 512, SM_GTOT>>>(
        nullptr, x, w16, nullptr);

    natt_all<<<dim3(IMG_W / 32, IMG_H / 4, NB * 6), dim3(32, 4)>>>(
        b0, b1, b2, b3, b4, b5);

    // d_out[b][ch][pix] = (attn @ w_out^T)^T
    mma_gemm<1><<<dim3(1, HW / 128, NB), 512, SM_GTOT>>>(
        at16, nullptr, w16 + 576 * CCH, (float*)d_out);
}